// round 9
// baseline (speedup 1.0000x reference)
#include <cuda_runtime.h>
#include <cstdint>

// Problem dims
#define Bb 8
#define Kk 1024
#define Ll 1024
#define Dd 1024
#define Oo 6
#define Ee 128
#define EPSf 1e-8f

// Scratch (device globals: allocation-free)
__device__ float g_priors[(size_t)Oo * Bb * Kk * Ee];  // [o][b][k][e]  (25 MB)
__device__ float g_logits[Bb * Kk * Oo];
__device__ float g_probs[Bb * Kk * Oo];                // [b][k][o]
__device__ float g_spart[16 * 48 * Ee];                // k-sliced partial sums

__device__ __forceinline__ unsigned f2tf32(float f) {
    unsigned r;
    asm("cvt.rna.tf32.f32 %0, %1;" : "=r"(r) : "f"(f));
    return r;
}

#if defined(__CUDA_ARCH__) && defined(__CUDA_ARCH_FEAT_SM103_ALL)
// ---------------------------------------------------------------------------
// tcgen05 helpers (only compiled in an sm_103a device pass)
// ---------------------------------------------------------------------------
__device__ __forceinline__ uint32_t smem_u32(const void* p) {
    uint32_t a;
    asm("{ .reg .u64 t; cvta.to.shared.u64 t, %1; cvt.u32.u64 %0, t; }" : "=r"(a) : "l"(p));
    return a;
}
__device__ __forceinline__ uint32_t elect1() {
    uint32_t p;
    asm volatile("{\n\t.reg .pred p;\n\telect.sync _|p, 0xFFFFFFFF;\n\tselp.b32 %0, 1, 0, p;\n\t}" : "=r"(p));
    return p;
}
#define SWZ(x) ((x) ^ (((x) >> 3) & 0x70u))

__device__ __forceinline__ void mbar_init(uint32_t a, uint32_t cnt) {
    asm volatile("mbarrier.init.shared.b64 [%0], %1;" :: "r"(a), "r"(cnt) : "memory");
}
__device__ __forceinline__ void mbar_wait(uint32_t a, uint32_t par) {
    uint32_t done;
    asm volatile(
        "{\n\t.reg .pred p;\n\t"
        "mbarrier.try_wait.parity.acquire.cta.shared::cta.b64 p, [%1], %2;\n\t"
        "selp.b32 %0, 1, 0, p;\n\t}"
        : "=r"(done) : "r"(a), "r"(par) : "memory");
    if (!done) {
        asm volatile(
            "{\n\t.reg .pred P1;\n\t"
            "WL%=:\n\t"
            "mbarrier.try_wait.parity.acquire.cta.shared::cta.b64 P1, [%0], %1, 0x989680;\n\t"
            "@P1 bra.uni WD%=;\n\t"
            "bra.uni WL%=;\n\t"
            "WD%=:\n\t}"
            :: "r"(a), "r"(par) : "memory");
    }
}
__device__ __forceinline__ void mma_tf32_ss(uint32_t d, uint64_t a, uint64_t b,
                                            uint32_t idesc, uint32_t en) {
    asm volatile(
        "{\n\t.reg .pred p;\n\tsetp.ne.u32 p, %5, 0;\n\t"
        "tcgen05.mma.cta_group::1.kind::tf32 [%0], %1, %2, %3, {%4, %4, %4, %4}, p;\n\t}"
        :: "r"(d), "l"(a), "l"(b), "r"(idesc), "r"(0u), "r"(en) : "memory");
}
__device__ __forceinline__ void tmem_ld32(uint32_t* r, uint32_t addr) {
    asm volatile(
        "tcgen05.ld.sync.aligned.32x32b.x32.b32 "
        "{%0, %1, %2, %3, %4, %5, %6, %7, "
        " %8, %9, %10, %11, %12, %13, %14, %15, "
        " %16, %17, %18, %19, %20, %21, %22, %23, "
        " %24, %25, %26, %27, %28, %29, %30, %31}, [%32];"
        : "=r"(r[0]),  "=r"(r[1]),  "=r"(r[2]),  "=r"(r[3]),
          "=r"(r[4]),  "=r"(r[5]),  "=r"(r[6]),  "=r"(r[7]),
          "=r"(r[8]),  "=r"(r[9]),  "=r"(r[10]), "=r"(r[11]),
          "=r"(r[12]), "=r"(r[13]), "=r"(r[14]), "=r"(r[15]),
          "=r"(r[16]), "=r"(r[17]), "=r"(r[18]), "=r"(r[19]),
          "=r"(r[20]), "=r"(r[21]), "=r"(r[22]), "=r"(r[23]),
          "=r"(r[24]), "=r"(r[25]), "=r"(r[26]), "=r"(r[27]),
          "=r"(r[28]), "=r"(r[29]), "=r"(r[30]), "=r"(r[31])
        : "r"(addr));
}
// SW128 K-major descriptor: layout=2, version=1, SBO=64, LBO=1
#define DESC_BASE ((2ull << 61) | (1ull << 46) | (64ull << 32) | (1ull << 16))
// idesc kind::tf32: F32 out (1<<4), TF32 a/b (2<<7 | 2<<10), N=128, M=128
#define IDESC_TF32 ((1u << 4) | (2u << 7) | (2u << 10) | ((Ee / 8) << 17) | (8u << 24))
#endif  // sm_103a helpers

// mma.sync fallback helper (all arches)
__device__ __forceinline__ void mma_tf32_sync(float* c, const unsigned* a, unsigned b0, unsigned b1) {
    asm volatile(
        "mma.sync.aligned.m16n8k8.row.col.f32.tf32.tf32.f32 "
        "{%0,%1,%2,%3}, {%4,%5,%6,%7}, {%8,%9}, {%0,%1,%2,%3};\n"
        : "+f"(c[0]), "+f"(c[1]), "+f"(c[2]), "+f"(c[3])
        : "r"(a[0]), "r"(a[1]), "r"(a[2]), "r"(a[3]), "r"(b0), "r"(b1));
}

// ---------------------------------------------------------------------------
// Kernel 1: priors GEMM.  grid (64 row-tiles of 128, 6 o) x 256 threads.
// C[128x128] = U_tile[128x1024] @ Wo[1024x128]; epilogue writes g_priors +
// fused iter-0 k-partials (2 x 64-row slices per tile; 16 per b).
// Path A: tcgen05 tf32 SS (sm_103a pass only). Path B: proven mma.sync tf32.
// ---------------------------------------------------------------------------
#define ASTRIDE 36   // 32 + 4 pad (fallback)
#define BSTRIDE 136  // 128 + 8 pad (fallback)

__global__ void __launch_bounds__(256) gemm_priors(const float* __restrict__ U,
                                                   const float* __restrict__ W) {
    const int o    = blockIdx.y;
    const int row0 = blockIdx.x * 128;
    const int b    = blockIdx.x >> 3;   // 8 tiles per b
    const int tile = blockIdx.x & 7;

    const int tid    = threadIdx.x;
    const int lane   = tid & 31;
    const int wid    = tid >> 5;
    const float* Wo = W + (size_t)o * Dd * Ee;

#if defined(__CUDA_ARCH__) && defined(__CUDA_ARCH_FEAT_SM103_ALL)
    // ======================= tcgen05 tf32 path =======================
    // smem: [0..15] tmem ptr, [16..31] 2 mbarriers, stages at 1024 (2 x 32KB:
    // A tile 16KB + B tile 16KB per stage).
    __shared__ __align__(1024) char smem[1024 + 2 * 32768];
    __shared__ float sums_s[8][64];
    const uint32_t sb = smem_u32(smem);

    if (wid == 0) {
        asm volatile("tcgen05.alloc.cta_group::1.sync.aligned.shared::cta.b32 [%0], %1;"
                     :: "r"(sb), "r"(128u) : "memory");
    }
    if (tid == 0) { mbar_init(sb + 16, 1); mbar_init(sb + 24, 1); }
    __syncthreads();
    uint32_t tmem;
    asm volatile("ld.shared.b32 %0, [%1];" : "=r"(tmem) : "r"(sb));

    int ph0 = 0, ph1 = 0;
    for (int c = 0; c < 32; c++) {
        const int s = c & 1;
        const uint32_t mb = sb + 16 + s * 8;
        if (c >= 2) {
            if (s) { mbar_wait(mb, ph1); ph1 ^= 1; }
            else   { mbar_wait(mb, ph0); ph0 ^= 1; }
        }
        const uint32_t stg = 1024 + s * 32768;
        // A: 128 m x 32 k tf32, SW128 (16KB). 4 float4 per thread.
#pragma unroll
        for (int i = 0; i < 4; i++) {
            int f = tid + i * 256;           // 0..1023
            int m = f >> 3;
            float4 a = *reinterpret_cast<const float4*>(
                &U[(size_t)(row0 + m) * Dd + c * 32 + (f & 7) * 4]);
            uint32_t byte = SWZ((uint32_t)(m * 128 + (f & 7) * 16)) + stg;
            *reinterpret_cast<uint4*>(smem + byte) =
                make_uint4(f2tf32(a.x), f2tf32(a.y), f2tf32(a.z), f2tf32(a.w));
        }
        // B: transpose Wo[k][e] -> [n=128 rows][k=32] SW128 (16KB)
#pragma unroll
        for (int i = 0; i < 4; i++) {
            int f  = tid + i * 256;          // 0..1023
            int k  = f >> 5;
            int e4 = (f & 31) * 4;
            float4 v = *reinterpret_cast<const float4*>(
                &Wo[(size_t)(c * 32 + k) * Ee + e4]);
            const uint32_t bbs = stg + 16384;
            *reinterpret_cast<uint32_t*>(smem + bbs + SWZ((uint32_t)((e4 + 0) * 128 + k * 4))) = f2tf32(v.x);
            *reinterpret_cast<uint32_t*>(smem + bbs + SWZ((uint32_t)((e4 + 1) * 128 + k * 4))) = f2tf32(v.y);
            *reinterpret_cast<uint32_t*>(smem + bbs + SWZ((uint32_t)((e4 + 2) * 128 + k * 4))) = f2tf32(v.z);
            *reinterpret_cast<uint32_t*>(smem + bbs + SWZ((uint32_t)((e4 + 3) * 128 + k * 4))) = f2tf32(v.w);
        }
        __syncthreads();
        if (wid == 0 && elect1()) {
            asm volatile("fence.proxy.async.shared::cta;" ::: "memory");
            uint64_t da = DESC_BASE | ((uint64_t)((sb + stg) >> 4) & 0x3FFF);
            uint64_t db = DESC_BASE | ((uint64_t)((sb + stg + 16384) >> 4) & 0x3FFF);
#pragma unroll
            for (int st = 0; st < 4; st++) {
                uint32_t en = (c | st) != 0;
                mma_tf32_ss(tmem, da + st * 2, db + st * 2, IDESC_TF32, en);
            }
            asm volatile("tcgen05.commit.cta_group::1.mbarrier::arrive::one.shared::cluster.b64 [%0];"
                         :: "r"(mb) : "memory");
        }
    }
    mbar_wait(sb + 24, ph1);   // final commit (chunk 31, stage 1); in-order covers 30
    asm volatile("tcgen05.fence::after_thread_sync;" ::: "memory");

    // Epilogue: warp w -> rows (w&3)*32+lane, cols (w>>2)*64 .. +63
    const int sub  = wid & 3;
    const int seg  = wid >> 2;
    float* dst = g_priors + ((size_t)o * (Bb * Kk) + row0 + sub * 32 + lane) * Ee + seg * 64;
#pragma unroll
    for (int cb = 0; cb < 2; cb++) {
        uint32_t r[32];
        tmem_ld32(r, tmem + seg * 64 + cb * 32);
        asm volatile("tcgen05.wait::ld.sync.aligned;" ::: "memory");
        float v[32];
#pragma unroll
        for (int j = 0; j < 32; j++) v[j] = __uint_as_float(r[j]);
#pragma unroll
        for (int q = 0; q < 8; q++)
            *reinterpret_cast<float4*>(dst + cb * 32 + q * 4) =
                make_float4(v[q * 4], v[q * 4 + 1], v[q * 4 + 2], v[q * 4 + 3]);
#pragma unroll
        for (int off = 16; off > 0; off >>= 1)
#pragma unroll
            for (int j = 0; j < 32; j++) v[j] += __shfl_xor_sync(0xffffffffu, v[j], off);
        if (lane == 0) {
#pragma unroll
            for (int j = 0; j < 32; j++) sums_s[wid][cb * 32 + j] = v[j];
        }
    }
    __syncthreads();
    if (tid < 256) {  // 2 slices x 128 e
        int hh = tid >> 7, e = tid & 127;
        int w0 = (e >> 6) * 4 + 2 * hh;
        float sv = sums_s[w0][e & 63] + sums_s[w0 + 1][e & 63];
        g_spart[((size_t)(tile * 2 + hh) * 48 + b * Oo + o) * Ee + e] = sv * (1.f / 6.f);
    }
    __syncthreads();
    if (wid == 0) {
        asm volatile("tcgen05.relinquish_alloc_permit.cta_group::1.sync.aligned;");
        asm volatile("tcgen05.dealloc.cta_group::1.sync.aligned.b32 %0, %1;" :: "r"(tmem), "r"(128u));
    }
#else
    // ======================= mma.sync fallback (proven) =======================
    __shared__ unsigned As[2][128 * ASTRIDE];
    __shared__ unsigned Bs[2][32 * BSTRIDE];

    const int warp_m = (wid & 3) * 32;
    const int warp_n = (wid >> 2) * 64;
    const int r      = lane >> 2;  // 0..7
    const int c4     = lane & 3;   // 0..3

    float acc[2][8][4];
#pragma unroll
    for (int i = 0; i < 2; i++)
#pragma unroll
        for (int j = 0; j < 8; j++)
#pragma unroll
            for (int q = 0; q < 4; q++) acc[i][j][q] = 0.f;

    float4 aST[4], bST[4];
#pragma unroll
    for (int i = 0; i < 4; i++) {
        int f = tid + i * 256;
        aST[i] = *reinterpret_cast<const float4*>(&U[(size_t)(row0 + (f >> 3)) * Dd + (f & 7) * 4]);
        bST[i] = *reinterpret_cast<const float4*>(&Wo[(size_t)(f >> 5) * Ee + (f & 31) * 4]);
    }
#pragma unroll
    for (int i = 0; i < 4; i++) {
        int f = tid + i * 256;
        *reinterpret_cast<uint4*>(&As[0][(f >> 3) * ASTRIDE + (f & 7) * 4]) =
            make_uint4(f2tf32(aST[i].x), f2tf32(aST[i].y), f2tf32(aST[i].z), f2tf32(aST[i].w));
        *reinterpret_cast<uint4*>(&Bs[0][(f >> 5) * BSTRIDE + (f & 31) * 4]) =
            make_uint4(f2tf32(bST[i].x), f2tf32(bST[i].y), f2tf32(bST[i].z), f2tf32(bST[i].w));
    }
    __syncthreads();

    for (int t = 0; t < 32; t++) {
        const int cur = t & 1;
        if (t < 31) {
            int k0 = (t + 1) * 32;
#pragma unroll
            for (int i = 0; i < 4; i++) {
                int f = tid + i * 256;
                aST[i] = *reinterpret_cast<const float4*>(&U[(size_t)(row0 + (f >> 3)) * Dd + k0 + (f & 7) * 4]);
                bST[i] = *reinterpret_cast<const float4*>(&Wo[(size_t)(k0 + (f >> 5)) * Ee + (f & 31) * 4]);
            }
        }
#pragma unroll
        for (int ks = 0; ks < 4; ks++) {
            const int kt = ks * 8;
            unsigned a[2][4];
#pragma unroll
            for (int i = 0; i < 2; i++) {
                int mb2 = warp_m + i * 16;
                a[i][0] = As[cur][(mb2 + r) * ASTRIDE + kt + c4];
                a[i][1] = As[cur][(mb2 + r + 8) * ASTRIDE + kt + c4];
                a[i][2] = As[cur][(mb2 + r) * ASTRIDE + kt + c4 + 4];
                a[i][3] = As[cur][(mb2 + r + 8) * ASTRIDE + kt + c4 + 4];
            }
#pragma unroll
            for (int j = 0; j < 8; j++) {
                int nb = warp_n + j * 8;
                unsigned b0 = Bs[cur][(kt + c4) * BSTRIDE + nb + r];
                unsigned b1 = Bs[cur][(kt + c4 + 4) * BSTRIDE + nb + r];
                mma_tf32_sync(acc[0][j], a[0], b0, b1);
                mma_tf32_sync(acc[1][j], a[1], b0, b1);
            }
        }
        if (t < 31) {
            const int nxt = 1 - cur;
#pragma unroll
            for (int i = 0; i < 4; i++) {
                int f = tid + i * 256;
                *reinterpret_cast<uint4*>(&As[nxt][(f >> 3) * ASTRIDE + (f & 7) * 4]) =
                    make_uint4(f2tf32(aST[i].x), f2tf32(aST[i].y), f2tf32(aST[i].z), f2tf32(aST[i].w));
                *reinterpret_cast<uint4*>(&Bs[nxt][(f >> 5) * BSTRIDE + (f & 31) * 4]) =
                    make_uint4(f2tf32(bST[i].x), f2tf32(bST[i].y), f2tf32(bST[i].z), f2tf32(bST[i].w));
            }
            __syncthreads();
        }
    }

    float* outp = g_priors + ((size_t)o * (Bb * Kk) + row0) * Ee;
#pragma unroll
    for (int i = 0; i < 2; i++) {
#pragma unroll
        for (int j = 0; j < 8; j++) {
            int m = warp_m + i * 16 + r;
            int n = warp_n + j * 8 + 2 * c4;
            *reinterpret_cast<float2*>(&outp[(size_t)m * Ee + n])       = make_float2(acc[i][j][0], acc[i][j][1]);
            *reinterpret_cast<float2*>(&outp[(size_t)(m + 8) * Ee + n]) = make_float2(acc[i][j][2], acc[i][j][3]);
        }
    }

    __shared__ float sacc2[2][128];
    __syncthreads();
    if (tid < 256) sacc2[tid >> 7][tid & 127] = 0.f;
    __syncthreads();

    const int h = (wid & 3) >> 1;
#pragma unroll
    for (int j = 0; j < 8; j++) {
        float v0 = acc[0][j][0] + acc[0][j][2] + acc[1][j][0] + acc[1][j][2];
        float v1 = acc[0][j][1] + acc[0][j][3] + acc[1][j][1] + acc[1][j][3];
#pragma unroll
        for (int off = 16; off >= 4; off >>= 1) {
            v0 += __shfl_down_sync(0xffffffffu, v0, off);
            v1 += __shfl_down_sync(0xffffffffu, v1, off);
        }
        if (lane < 4) {
            atomicAdd(&sacc2[h][warp_n + j * 8 + 2 * lane], v0);
            atomicAdd(&sacc2[h][warp_n + j * 8 + 2 * lane + 1], v1);
        }
    }
    __syncthreads();
    if (tid < 256) {
        int hh = tid >> 7, e = tid & 127;
        g_spart[((size_t)(tile * 2 + hh) * 48 + b * Oo + o) * Ee + e] = sacc2[hh][e] * (1.f / 6.f);
    }
#endif
}

// ---------------------------------------------------------------------------
// Kernel 2: fused routing iteration with inline v computation.
// grid (8 b, 16 sl) x 256 threads.
// ---------------------------------------------------------------------------
__global__ void __launch_bounds__(256) fused_iter(const int* __restrict__ mask, int first) {
    const int b    = blockIdx.x;
    const int sl   = blockIdx.y;   // 0..15
    const int tid  = threadIdx.x;
    const int w    = tid >> 5;
    const int lane = tid & 31;

    __shared__ float vsh[Oo * Ee];

    for (int i = tid; i < Oo * Ee; i += 256) {
        int o = i >> 7, e = i & 127;
        float s = 0.f;
#pragma unroll
        for (int q = 0; q < 16; q++)
            s += g_spart[(q * 48 + b * Oo + o) * Ee + e];
        vsh[i] = s;
    }
    __syncthreads();
    if (w < Oo) {
        float4 sv = *reinterpret_cast<float4*>(&vsh[w * Ee + lane * 4]);
        float x2 = sv.x * sv.x + sv.y * sv.y + sv.z * sv.z + sv.w * sv.w;
#pragma unroll
        for (int off = 16; off > 0; off >>= 1)
            x2 += __shfl_xor_sync(0xffffffffu, x2, off);
        float coef = x2 / ((1.f + x2) * (sqrtf(x2) + EPSf));
        sv.x *= coef; sv.y *= coef; sv.z *= coef; sv.w *= coef;
        *reinterpret_cast<float4*>(&vsh[w * Ee + lane * 4]) = sv;
    }
    __syncthreads();

    float4 vv[Oo];
#pragma unroll
    for (int o = 0; o < Oo; o++)
        vv[o] = *reinterpret_cast<const float4*>(&vsh[o * Ee + lane * 4]);

    float4 sacc[Oo];
#pragma unroll
    for (int o = 0; o < Oo; o++) sacc[o] = make_float4(0.f, 0.f, 0.f, 0.f);

#pragma unroll 1
    for (int t = 0; t < 8; t++) {
        const int k   = sl * 64 + w * 8 + t;
        const int idx = b * Kk + k;

        float4 P4[Oo];
#pragma unroll
        for (int o = 0; o < Oo; o++)
            P4[o] = *reinterpret_cast<const float4*>(
                &g_priors[((size_t)(o * Bb + b) * Kk + k) * Ee + lane * 4]);

        const int m = mask[idx];
        float p[Oo];
        if (m) {
#pragma unroll
            for (int o = 0; o < Oo; o++) p[o] = 1.f / 6.f;
        } else {
            float d[Oo];
#pragma unroll
            for (int o = 0; o < Oo; o++)
                d[o] = P4[o].x * vv[o].x + P4[o].y * vv[o].y + P4[o].z * vv[o].z + P4[o].w * vv[o].w;
#pragma unroll
            for (int off = 16; off > 0; off >>= 1)
#pragma unroll
                for (int o = 0; o < Oo; o++)
                    d[o] += __shfl_xor_sync(0xffffffffu, d[o], off);

            float lg[Oo];
            if (first) {
#pragma unroll
                for (int o = 0; o < Oo; o++) lg[o] = d[o];
            } else {
                float myold = (lane < Oo) ? g_logits[(size_t)idx * Oo + lane] : 0.f;
#pragma unroll
                for (int o = 0; o < Oo; o++)
                    lg[o] = __shfl_sync(0xffffffffu, myold, o) + d[o];
            }
            if (lane < Oo) g_logits[(size_t)idx * Oo + lane] = lg[lane];

            float mx = lg[0];
#pragma unroll
            for (int o = 1; o < Oo; o++) mx = fmaxf(mx, lg[o]);
            float sum = 0.f;
#pragma unroll
            for (int o = 0; o < Oo; o++) { p[o] = __expf(lg[o] - mx); sum += p[o]; }
            float inv = 1.f / sum;
#pragma unroll
            for (int o = 0; o < Oo; o++) p[o] *= inv;
        }

        if (lane < Oo) g_probs[(size_t)idx * Oo + lane] = p[lane];

#pragma unroll
        for (int o = 0; o < Oo; o++) {
            sacc[o].x += p[o] * P4[o].x;
            sacc[o].y += p[o] * P4[o].y;
            sacc[o].z += p[o] * P4[o].z;
            sacc[o].w += p[o] * P4[o].w;
        }
    }

    __shared__ float sred[8][Oo * Ee];
#pragma unroll
    for (int o = 0; o < Oo; o++)
        *reinterpret_cast<float4*>(&sred[w][o * Ee + lane * 4]) = sacc[o];
    __syncthreads();

    for (int i = tid; i < Oo * Ee; i += 256) {
        float s = 0.f;
#pragma unroll
        for (int ww = 0; ww < 8; ww++) s += sred[ww][i];
        g_spart[(sl * 48 + b * Oo + (i >> 7)) * Ee + (i & 127)] = s;
    }
}

// ---------------------------------------------------------------------------
// Kernel 3: final squash + v broadcast, parallel over L. grid (48, 8) x 256.
// ---------------------------------------------------------------------------
__global__ void __launch_bounds__(256) squash_bcast_v(float* __restrict__ out_v) {
    const int bo  = blockIdx.x;  // b*Oo + o
    const int lc  = blockIdx.y;  // 0..7
    const int b   = bo / Oo;
    const int o   = bo % Oo;
    const int tid = threadIdx.x;

    __shared__ float s_store[Ee];
    __shared__ float ws[4];
    __shared__ float vsh[Ee];

    if (tid < 128) {
        float s = 0.f;
#pragma unroll
        for (int q = 0; q < 16; q++)
            s += g_spart[(q * 48 + bo) * Ee + tid];
        s_store[tid] = s;
        float x2 = s * s;
#pragma unroll
        for (int off = 16; off > 0; off >>= 1)
            x2 += __shfl_xor_sync(0xffffffffu, x2, off);
        if ((tid & 31) == 0) ws[tid >> 5] = x2;
    }
    __syncthreads();
    if (tid < 128) {
        float sq   = ws[0] + ws[1] + ws[2] + ws[3];
        float coef = sq / ((1.f + sq) * (sqrtf(sq) + EPSf));
        vsh[tid]   = s_store[tid] * coef;
    }
    __syncthreads();

    const float4 myval = reinterpret_cast<const float4*>(vsh)[tid & 31];
    for (int idx = tid; idx < 128 * 32; idx += 256) {
        int l = lc * 128 + (idx >> 5);
        reinterpret_cast<float4*>(out_v)[((size_t)(b * Ll + l) * Oo + o) * 32 + (tid & 31)] = myval;
    }
}

// ---------------------------------------------------------------------------
// Kernel 4: broadcast probs[b,k,o] -> out_p[b,l,k,o]
// ---------------------------------------------------------------------------
__global__ void __launch_bounds__(256) bcast_probs(float* __restrict__ out, int bl0) {
    const int bl = bl0 + blockIdx.x;  // b*L + l
    const int b  = bl >> 10;
    const float4* src = reinterpret_cast<const float4*>(g_probs + (size_t)b * (Kk * Oo));
    float4* dst       = reinterpret_cast<float4*>(out + (size_t)bl * (Kk * Oo));
#pragma unroll
    for (int i = threadIdx.x; i < (Kk * Oo / 4); i += 256)
        dst[i] = src[i];
}

// ---------------------------------------------------------------------------
extern "C" void kernel_launch(void* const* d_in, const int* in_sizes, int n_in,
                              void* d_out, int out_size) {
    const float* U = (const float*)d_in[0];               // inputs_u (B,K,D)
    // d_in[1] = context_sequence : provably unused by the reference math
    const float* W = (const float*)d_in[2];               // route_weights (O,D,E)
    const int* mask = (const int*)d_in[3];                // inputs_mask (B,K), bool->int32

    float* out_v = (float*)d_out;                                   // (B,L,O,E)
    float* out_p = (float*)d_out + (size_t)Bb * Ll * Oo * Ee;       // (B,L,K,O)

    // 1. priors GEMM (tcgen05 if sm_103a pass exists, else mma.sync) + iter-0 partials
    gemm_priors<<<dim3((Bb * Kk) / 128, Oo), 256>>>(U, W);

    // 2. Routing iterations; v computed inline from spart each time
    fused_iter<<<dim3(Bb, 16), 256>>>(mask, 1);  // v0 -> logits1, probs1, spart
    fused_iter<<<dim3(Bb, 16), 256>>>(mask, 0);  // v1 -> logits2, probs2, spart

    // 3. Final squash + v broadcast (parallel over L); probs broadcast
    squash_bcast_v<<<dim3(48, 8), 256>>>(out_v);
    bcast_probs<<<Bb * Ll / 2, 256>>>(out_p, 0);
    bcast_probs<<<Bb * Ll / 2, 256>>>(out_p, Bb * Ll / 2);
}

// round 10
// speedup vs baseline: 1.3176x; 1.3176x over previous
#include <cuda_runtime.h>
#include <cstdint>

// Problem dims
#define Bb 8
#define Kk 1024
#define Ll 1024
#define Dd 1024
#define Oo 6
#define Ee 128
#define EPSf 1e-8f

// Scratch (device globals: allocation-free)
__device__ float g_priors[(size_t)Oo * Bb * Kk * Ee];  // [o][b][k][e]  (25 MB)
__device__ float g_logits[Bb * Kk * Oo];
__device__ float g_probs[Bb * Kk * Oo];                // [b][k][o]
__device__ float g_spart[16 * 48 * Ee];                // k-sliced partial sums

__device__ __forceinline__ unsigned f2tf32(float f) {
    unsigned r;
    asm("cvt.rna.tf32.f32 %0, %1;" : "=r"(r) : "f"(f));
    return r;
}
__device__ __forceinline__ void mma_tf32(float* c, const unsigned* a, unsigned b0, unsigned b1) {
    asm volatile(
        "mma.sync.aligned.m16n8k8.row.col.f32.tf32.tf32.f32 "
        "{%0,%1,%2,%3}, {%4,%5,%6,%7}, {%8,%9}, {%0,%1,%2,%3};\n"
        : "+f"(c[0]), "+f"(c[1]), "+f"(c[2]), "+f"(c[3])
        : "r"(a[0]), "r"(a[1]), "r"(a[2]), "r"(a[3]), "r"(b0), "r"(b1));
}

// ---------------------------------------------------------------------------
// Kernel 1: priors GEMM, tf32 mma.sync, warp tile 64m x 32n (2m x 4n warps),
// fragment-packed A (LDS.128 per fragment, ks-XOR bank swizzle), double-
// buffered smem, fused iter-0 k-partials (warp-local, no atomics).
// grid (64 row-tiles of 128, 6 o) x 256 threads.
//
// A-frag layout (words): addr = (fb*4 + ks)*128 + rr*16 + ((cc^ks)&3)*4 + pq
//   fb = m>>4, rr = m&7, p = (m>>3)&1, ks = k>>3, q = (k>>2)&1, cc = k&3,
//   pq = p + 2q.  A fragment (fixed fb,ks,rr,cc') is 4 contiguous words
//   [pq=0..3] = [(r,c),(r+8,c),(r,c+4),(r+8,c+4)] -> one LDS.128.
// ---------------------------------------------------------------------------
#define BSTRIDE 136  // 128 + 8 pad -> conflict-free scalar B loads

__global__ void __launch_bounds__(256) gemm_priors(const float* __restrict__ U,
                                                   const float* __restrict__ W) {
    const int o    = blockIdx.y;
    const int row0 = blockIdx.x * 128;
    const int b    = blockIdx.x >> 3;   // 8 tiles per b
    const int tile = blockIdx.x & 7;

    const int tid  = threadIdx.x;
    const int lane = tid & 31;
    const int wid  = tid >> 5;
    const int mw     = wid & 1;          // m-warp: rows mw*64 .. +63
    const int warp_n = (wid >> 1) * 32;  // n-warp: cols warp_n .. +31
    const int r    = lane >> 2;          // 0..7
    const int c    = lane & 3;           // 0..3

    __shared__ unsigned Af[2][4096];            // packed A, 16KB per stage
    __shared__ unsigned Bs[2][32 * BSTRIDE];    // [k][n] B, 17KB per stage

    const float* Wo = W + (size_t)o * Dd * Ee;

    float acc[4][4][4];  // [i m-frag][j n-frag][4]
#pragma unroll
    for (int i = 0; i < 4; i++)
#pragma unroll
        for (int j = 0; j < 4; j++)
#pragma unroll
            for (int q = 0; q < 4; q++) acc[i][j][q] = 0.f;

    float4 aST[4], bST[4];

    // ---- staging helpers (as macros over aST/bST) ----
#define LOAD_TILE(k0)                                                                   \
    {                                                                                   \
        _Pragma("unroll")                                                               \
        for (int i_ = 0; i_ < 4; i_++) {                                                \
            int f = tid + i_ * 256;                                                     \
            aST[i_] = *reinterpret_cast<const float4*>(                                 \
                &U[(size_t)(row0 + (f >> 3)) * Dd + (k0) + (f & 7) * 4]);               \
            bST[i_] = *reinterpret_cast<const float4*>(                                 \
                &Wo[(size_t)((k0) + (f >> 5)) * Ee + (f & 31) * 4]);                    \
        }                                                                               \
    }
#define STORE_TILE(buf)                                                                 \
    {                                                                                   \
        _Pragma("unroll")                                                               \
        for (int i_ = 0; i_ < 4; i_++) {                                                \
            int f  = tid + i_ * 256;                                                    \
            int m  = f >> 3;                                                            \
            int g  = f & 7;                                                             \
            int ks = g >> 1;                                                            \
            int base = (((m >> 4) * 4 + ks) * 128) + (m & 7) * 16 +                     \
                       (((m >> 3) & 1) + 2 * (g & 1));                                  \
            Af[buf][base + (((0 ^ ks) & 3) * 4)] = f2tf32(aST[i_].x);                   \
            Af[buf][base + (((1 ^ ks) & 3) * 4)] = f2tf32(aST[i_].y);                   \
            Af[buf][base + (((2 ^ ks) & 3) * 4)] = f2tf32(aST[i_].z);                   \
            Af[buf][base + (((3 ^ ks) & 3) * 4)] = f2tf32(aST[i_].w);                   \
            *reinterpret_cast<uint4*>(&Bs[buf][(f >> 5) * BSTRIDE + (f & 31) * 4]) =    \
                make_uint4(f2tf32(bST[i_].x), f2tf32(bST[i_].y),                        \
                           f2tf32(bST[i_].z), f2tf32(bST[i_].w));                       \
        }                                                                               \
    }

    LOAD_TILE(0);
    STORE_TILE(0);
    __syncthreads();

    for (int t = 0; t < 32; t++) {
        const int cur = t & 1;
        if (t < 31) LOAD_TILE((t + 1) * 32);

#pragma unroll
        for (int ks = 0; ks < 4; ks++) {
            const int kt = ks * 8;
            uint4 afr[4];
#pragma unroll
            for (int i = 0; i < 4; i++)
                afr[i] = *reinterpret_cast<const uint4*>(
                    &Af[cur][((mw * 4 + i) * 4 + ks) * 128 + r * 16 + ((c ^ ks) & 3) * 4]);
#pragma unroll
            for (int j = 0; j < 4; j++) {
                const int nb = warp_n + j * 8;
                unsigned b0 = Bs[cur][(kt + c) * BSTRIDE + nb + r];
                unsigned b1 = Bs[cur][(kt + c + 4) * BSTRIDE + nb + r];
#pragma unroll
                for (int i = 0; i < 4; i++)
                    mma_tf32(acc[i][j], reinterpret_cast<const unsigned*>(&afr[i]), b0, b1);
            }
        }

        if (t < 31) {
            STORE_TILE(1 - cur);
            __syncthreads();
        }
    }

    // write C: rows mw*64 + i*16 + {r, r+8}, cols warp_n + j*8 + {2c, 2c+1}
    float* outp = g_priors + ((size_t)o * (Bb * Kk) + row0) * Ee;
#pragma unroll
    for (int i = 0; i < 4; i++) {
#pragma unroll
        for (int j = 0; j < 4; j++) {
            int m = mw * 64 + i * 16 + r;
            int n = warp_n + j * 8 + 2 * c;
            *reinterpret_cast<float2*>(&outp[(size_t)m * Ee + n])       = make_float2(acc[i][j][0], acc[i][j][1]);
            *reinterpret_cast<float2*>(&outp[(size_t)(m + 8) * Ee + n]) = make_float2(acc[i][j][2], acc[i][j][3]);
        }
    }

    // fused iter-0 k-partials: each warp covers a FULL 64-row half (i spans 64
    // rows) and 32 distinct columns -> warp-local column sums, direct store.
    {
        const int h = mw;  // 64-row half index
#pragma unroll
        for (int j = 0; j < 4; j++) {
            float s0 = 0.f, s1 = 0.f;
#pragma unroll
            for (int i = 0; i < 4; i++) {
                s0 += acc[i][j][0] + acc[i][j][2];
                s1 += acc[i][j][1] + acc[i][j][3];
            }
#pragma unroll
            for (int off = 4; off <= 16; off <<= 1) {  // reduce over r (lane bits 2..4)
                s0 += __shfl_xor_sync(0xffffffffu, s0, off);
                s1 += __shfl_xor_sync(0xffffffffu, s1, off);
            }
            if (lane < 4) {
                int col = warp_n + j * 8 + 2 * lane;
                float* sp = &g_spart[((size_t)(tile * 2 + h) * 48 + b * Oo + o) * Ee];
                sp[col]     = s0 * (1.f / 6.f);
                sp[col + 1] = s1 * (1.f / 6.f);
            }
        }
    }
#undef LOAD_TILE
#undef STORE_TILE
}

// ---------------------------------------------------------------------------
// Kernel 2: fused routing iteration with inline v computation.
// grid (8 b, 16 sl) x 256 threads.
// ---------------------------------------------------------------------------
__global__ void __launch_bounds__(256) fused_iter(const int* __restrict__ mask, int first) {
    const int b    = blockIdx.x;
    const int sl   = blockIdx.y;   // 0..15
    const int tid  = threadIdx.x;
    const int w    = tid >> 5;
    const int lane = tid & 31;

    __shared__ float vsh[Oo * Ee];

    for (int i = tid; i < Oo * Ee; i += 256) {
        int o = i >> 7, e = i & 127;
        float s = 0.f;
#pragma unroll
        for (int q = 0; q < 16; q++)
            s += g_spart[(q * 48 + b * Oo + o) * Ee + e];
        vsh[i] = s;
    }
    __syncthreads();
    if (w < Oo) {
        float4 sv = *reinterpret_cast<float4*>(&vsh[w * Ee + lane * 4]);
        float x2 = sv.x * sv.x + sv.y * sv.y + sv.z * sv.z + sv.w * sv.w;
#pragma unroll
        for (int off = 16; off > 0; off >>= 1)
            x2 += __shfl_xor_sync(0xffffffffu, x2, off);
        float coef = x2 / ((1.f + x2) * (sqrtf(x2) + EPSf));
        sv.x *= coef; sv.y *= coef; sv.z *= coef; sv.w *= coef;
        *reinterpret_cast<float4*>(&vsh[w * Ee + lane * 4]) = sv;
    }
    __syncthreads();

    float4 vv[Oo];
#pragma unroll
    for (int o = 0; o < Oo; o++)
        vv[o] = *reinterpret_cast<const float4*>(&vsh[o * Ee + lane * 4]);

    float4 sacc[Oo];
#pragma unroll
    for (int o = 0; o < Oo; o++) sacc[o] = make_float4(0.f, 0.f, 0.f, 0.f);

#pragma unroll 1
    for (int t = 0; t < 8; t++) {
        const int k   = sl * 64 + w * 8 + t;
        const int idx = b * Kk + k;

        float4 P4[Oo];
#pragma unroll
        for (int o = 0; o < Oo; o++)
            P4[o] = *reinterpret_cast<const float4*>(
                &g_priors[((size_t)(o * Bb + b) * Kk + k) * Ee + lane * 4]);

        const int m = mask[idx];
        float p[Oo];
        if (m) {
#pragma unroll
            for (int o = 0; o < Oo; o++) p[o] = 1.f / 6.f;
        } else {
            float d[Oo];
#pragma unroll
            for (int o = 0; o < Oo; o++)
                d[o] = P4[o].x * vv[o].x + P4[o].y * vv[o].y + P4[o].z * vv[o].z + P4[o].w * vv[o].w;
#pragma unroll
            for (int off = 16; off > 0; off >>= 1)
#pragma unroll
                for (int o = 0; o < Oo; o++)
                    d[o] += __shfl_xor_sync(0xffffffffu, d[o], off);

            float lg[Oo];
            if (first) {
#pragma unroll
                for (int o = 0; o < Oo; o++) lg[o] = d[o];
            } else {
                float myold = (lane < Oo) ? g_logits[(size_t)idx * Oo + lane] : 0.f;
#pragma unroll
                for (int o = 0; o < Oo; o++)
                    lg[o] = __shfl_sync(0xffffffffu, myold, o) + d[o];
            }
            if (lane < Oo) g_logits[(size_t)idx * Oo + lane] = lg[lane];

            float mx = lg[0];
#pragma unroll
            for (int o = 1; o < Oo; o++) mx = fmaxf(mx, lg[o]);
            float sum = 0.f;
#pragma unroll
            for (int o = 0; o < Oo; o++) { p[o] = __expf(lg[o] - mx); sum += p[o]; }
            float inv = 1.f / sum;
#pragma unroll
            for (int o = 0; o < Oo; o++) p[o] *= inv;
        }

        if (lane < Oo) g_probs[(size_t)idx * Oo + lane] = p[lane];

#pragma unroll
        for (int o = 0; o < Oo; o++) {
            sacc[o].x += p[o] * P4[o].x;
            sacc[o].y += p[o] * P4[o].y;
            sacc[o].z += p[o] * P4[o].z;
            sacc[o].w += p[o] * P4[o].w;
        }
    }

    __shared__ float sred[8][Oo * Ee];
#pragma unroll
    for (int o = 0; o < Oo; o++)
        *reinterpret_cast<float4*>(&sred[w][o * Ee + lane * 4]) = sacc[o];
    __syncthreads();

    for (int i = tid; i < Oo * Ee; i += 256) {
        float s = 0.f;
#pragma unroll
        for (int ww = 0; ww < 8; ww++) s += sred[ww][i];
        g_spart[(sl * 48 + b * Oo + (i >> 7)) * Ee + (i & 127)] = s;
    }
}

// ---------------------------------------------------------------------------
// Kernel 3: final squash + v broadcast, parallel over L. grid (48, 8) x 256.
// ---------------------------------------------------------------------------
__global__ void __launch_bounds__(256) squash_bcast_v(float* __restrict__ out_v) {
    const int bo  = blockIdx.x;  // b*Oo + o
    const int lc  = blockIdx.y;  // 0..7
    const int b   = bo / Oo;
    const int o   = bo % Oo;
    const int tid = threadIdx.x;

    __shared__ float s_store[Ee];
    __shared__ float ws[4];
    __shared__ float vsh[Ee];

    if (tid < 128) {
        float s = 0.f;
#pragma unroll
        for (int q = 0; q < 16; q++)
            s += g_spart[(q * 48 + bo) * Ee + tid];
        s_store[tid] = s;
        float x2 = s * s;
#pragma unroll
        for (int off = 16; off > 0; off >>= 1)
            x2 += __shfl_xor_sync(0xffffffffu, x2, off);
        if ((tid & 31) == 0) ws[tid >> 5] = x2;
    }
    __syncthreads();
    if (tid < 128) {
        float sq   = ws[0] + ws[1] + ws[2] + ws[3];
        float coef = sq / ((1.f + sq) * (sqrtf(sq) + EPSf));
        vsh[tid]   = s_store[tid] * coef;
    }
    __syncthreads();

    const float4 myval = reinterpret_cast<const float4*>(vsh)[tid & 31];
    for (int idx = tid; idx < 128 * 32; idx += 256) {
        int l = lc * 128 + (idx >> 5);
        reinterpret_cast<float4*>(out_v)[((size_t)(b * Ll + l) * Oo + o) * 32 + (tid & 31)] = myval;
    }
}

// ---------------------------------------------------------------------------
// Kernel 4: broadcast probs[b,k,o] -> out_p[b,l,k,o].
// One block per (b, 8 l's): stage the 24KB slice in registers, write 8x.
// Cuts L2 read traffic 8x vs per-l blocks.
// ---------------------------------------------------------------------------
__global__ void __launch_bounds__(256) bcast_probs(float* __restrict__ out, int blk0) {
    const int blk = blk0 + blockIdx.x;   // 0..1023
    const int b   = blk >> 7;            // 128 l-groups per b
    const int lg  = blk & 127;
    const int tid = threadIdx.x;

    const float4* src = reinterpret_cast<const float4*>(g_probs) + (size_t)b * (Kk * Oo / 4);
    float4 v[6];
#pragma unroll
    for (int q = 0; q < 6; q++) v[q] = src[tid + q * 256];

#pragma unroll
    for (int l = 0; l < 8; l++) {
        float4* dst = reinterpret_cast<float4*>(out) +
                      ((size_t)(b * Ll + lg * 8 + l)) * (Kk * Oo / 4);
#pragma unroll
        for (int q = 0; q < 6; q++) dst[tid + q * 256] = v[q];
    }
}

// ---------------------------------------------------------------------------
extern "C" void kernel_launch(void* const* d_in, const int* in_sizes, int n_in,
                              void* d_out, int out_size) {
    const float* U = (const float*)d_in[0];               // inputs_u (B,K,D)
    // d_in[1] = context_sequence : provably unused by the reference math
    const float* W = (const float*)d_in[2];               // route_weights (O,D,E)
    const int* mask = (const int*)d_in[3];                // inputs_mask (B,K), bool->int32

    float* out_v = (float*)d_out;                                   // (B,L,O,E)
    float* out_p = (float*)d_out + (size_t)Bb * Ll * Oo * Ee;       // (B,L,K,O)

    // 1. priors GEMM (tf32 mma.sync, packed-A) + fused iter-0 k-partials
    gemm_priors<<<dim3((Bb * Kk) / 128, Oo), 256>>>(U, W);

    // 2. Routing iterations; v computed inline from spart each time
    fused_iter<<<dim3(Bb, 16), 256>>>(mask, 1);  // v0 -> logits1, probs1, spart
    fused_iter<<<dim3(Bb, 16), 256>>>(mask, 0);  // v1 -> logits2, probs2, spart

    // 3. Final squash + v broadcast (parallel over L); probs broadcast
    squash_bcast_v<<<dim3(48, 8), 256>>>(out_v);
    bcast_probs<<<512, 256>>>(out_p, 0);
    bcast_probs<<<512, 256>>>(out_p, 512);
}

// round 11
// speedup vs baseline: 1.7632x; 1.3382x over previous
#include <cuda_runtime.h>
#include <cuda_fp16.h>
#include <cstdint>

// Problem dims
#define Bb 8
#define Kk 1024
#define Ll 1024
#define Dd 1024
#define Oo 6
#define Ee 128
#define EPSf 1e-8f

// Scratch (device globals: allocation-free)
__device__ float g_priors[(size_t)Oo * Bb * Kk * Ee];  // [o][b][k][e]  (25 MB)
__device__ float g_logits[Bb * Kk * Oo];
__device__ float g_probs[Bb * Kk * Oo];                // [b][k][o]
__device__ float g_spart[16 * 48 * Ee];                // k-sliced partial sums

__device__ __forceinline__ unsigned packh2(float lo, float hi) {
    __half2 t = __floats2half2_rn(lo, hi);   // .x = lo (low 16 bits), .y = hi
    return *reinterpret_cast<unsigned*>(&t);
}
__device__ __forceinline__ void mma_f16(float* c, const unsigned* a, unsigned b0, unsigned b1) {
    asm volatile(
        "mma.sync.aligned.m16n8k16.row.col.f32.f16.f16.f32 "
        "{%0,%1,%2,%3}, {%4,%5,%6,%7}, {%8,%9}, {%0,%1,%2,%3};\n"
        : "+f"(c[0]), "+f"(c[1]), "+f"(c[2]), "+f"(c[3])
        : "r"(a[0]), "r"(a[1]), "r"(a[2]), "r"(a[3]), "r"(b0), "r"(b1));
}

// ---------------------------------------------------------------------------
// Kernel 1: priors GEMM, fp16 mma.sync m16n8k16 (fp32 accum), warp tile
// 64m x 32n (2m x 4n warps), fragment-packed A (one LDS.128 per A fragment),
// k-pair-packed B (one LDS.32 per B reg), double-buffered smem, fused iter-0
// k-partials (warp-local, no atomics).
// grid (64 row-tiles of 128, 6 o) x 256 threads.
//
// fp16 rationale: same 11-bit significand as tf32 (inputs are O(1), well in
// range), but 2x FLOPs per MMA instruction -> halves the MMA issue count.
//
// A-frag layout (uint words, per 32-k tile): fragment (fb, ks, r, c) is 4
// consecutive words at  (fb*2+ks)*128 + r*16 + c*4 ,
//   word q = pr + 2*cq : [(r, pair c), (r+8, pair c), (r, pair c+4), (r+8, pair c+4)]
// matching m16n8k16 operands {a0,a1,a2,a3}. pair p = k-pair index (k/2 in tile).
//
// B layout: Bp[kp][n] uint = half2( W[2kp][n], W[2kp+1][n] ), row pad 132.
//   b0 = Bp[ks*8 + c][nb + r],  b1 = Bp[ks*8 + c + 4][nb + r].
// ---------------------------------------------------------------------------
#define BPAD 132

__global__ void __launch_bounds__(256) gemm_priors(const float* __restrict__ U,
                                                   const float* __restrict__ W) {
    const int o    = blockIdx.y;
    const int row0 = blockIdx.x * 128;
    const int b    = blockIdx.x >> 3;   // 8 tiles per b
    const int tile = blockIdx.x & 7;

    const int tid  = threadIdx.x;
    const int lane = tid & 31;
    const int wid  = tid >> 5;
    const int mw     = wid & 1;          // m-warp: rows mw*64 .. +63
    const int warp_n = (wid >> 1) * 32;  // n-warp: cols warp_n .. +31
    const int r    = lane >> 2;          // 0..7
    const int c    = lane & 3;           // 0..3

    __shared__ unsigned Af[2][2048];         // packed A halves, 8KB per stage
    __shared__ unsigned Bp[2][16 * BPAD];    // packed B halves, 8.25KB per stage

    const float* Wo = W + (size_t)o * Dd * Ee;

    float acc[4][4][4];  // [i m-frag][j n-frag][4]
#pragma unroll
    for (int i = 0; i < 4; i++)
#pragma unroll
        for (int j = 0; j < 4; j++)
#pragma unroll
            for (int q = 0; q < 4; q++) acc[i][j][q] = 0.f;

    float4 aST[4], bLO[2], bHI[2];

#define LOAD_TILE(k0)                                                                   \
    {                                                                                   \
        _Pragma("unroll")                                                               \
        for (int i_ = 0; i_ < 4; i_++) {                                                \
            int f = tid + i_ * 256;                                                     \
            aST[i_] = *reinterpret_cast<const float4*>(                                 \
                &U[(size_t)(row0 + (f >> 3)) * Dd + (k0) + (f & 7) * 4]);               \
        }                                                                               \
        _Pragma("unroll")                                                               \
        for (int i_ = 0; i_ < 2; i_++) {                                                \
            int f  = tid + i_ * 256;                                                    \
            int kp = f >> 5;                                                            \
            int n4 = (f & 31) * 4;                                                      \
            bLO[i_] = *reinterpret_cast<const float4*>(                                 \
                &Wo[(size_t)((k0) + 2 * kp) * Ee + n4]);                                \
            bHI[i_] = *reinterpret_cast<const float4*>(                                 \
                &Wo[(size_t)((k0) + 2 * kp + 1) * Ee + n4]);                            \
        }                                                                               \
    }
#define STORE_TILE(buf)                                                                 \
    {                                                                                   \
        _Pragma("unroll")                                                               \
        for (int i_ = 0; i_ < 4; i_++) {                                                \
            int f  = tid + i_ * 256;                                                    \
            int m  = f >> 3;                                                            \
            int g  = f & 7;                                                             \
            int ks = g >> 2;                                                            \
            int p0 = (g & 3) * 2;                                                       \
            int base = ((m >> 4) * 2 + ks) * 128 + (m & 7) * 16 + ((m >> 3) & 1);       \
            Af[buf][base + (p0 & 3) * 4 + 2 * (p0 >> 2)] = packh2(aST[i_].x, aST[i_].y);\
            int p1 = p0 + 1;                                                            \
            Af[buf][base + (p1 & 3) * 4 + 2 * (p1 >> 2)] = packh2(aST[i_].z, aST[i_].w);\
        }                                                                               \
        _Pragma("unroll")                                                               \
        for (int i_ = 0; i_ < 2; i_++) {                                                \
            int f  = tid + i_ * 256;                                                    \
            int kp = f >> 5;                                                            \
            int n4 = (f & 31) * 4;                                                      \
            *reinterpret_cast<uint4*>(&Bp[buf][kp * BPAD + n4]) =                       \
                make_uint4(packh2(bLO[i_].x, bHI[i_].x), packh2(bLO[i_].y, bHI[i_].y),  \
                           packh2(bLO[i_].z, bHI[i_].z), packh2(bLO[i_].w, bHI[i_].w)); \
        }                                                                               \
    }

    LOAD_TILE(0);
    STORE_TILE(0);
    __syncthreads();

    for (int t = 0; t < 32; t++) {
        const int cur = t & 1;
        if (t < 31) LOAD_TILE((t + 1) * 32);

#pragma unroll
        for (int ks = 0; ks < 2; ks++) {   // two k16 steps per 32-k tile
            uint4 afr[4];
#pragma unroll
            for (int i = 0; i < 4; i++)
                afr[i] = *reinterpret_cast<const uint4*>(
                    &Af[cur][((mw * 4 + i) * 2 + ks) * 128 + r * 16 + c * 4]);
#pragma unroll
            for (int j = 0; j < 4; j++) {
                const int nb = warp_n + j * 8;
                unsigned b0 = Bp[cur][(ks * 8 + c) * BPAD + nb + r];
                unsigned b1 = Bp[cur][(ks * 8 + c + 4) * BPAD + nb + r];
#pragma unroll
                for (int i = 0; i < 4; i++)
                    mma_f16(acc[i][j], reinterpret_cast<const unsigned*>(&afr[i]), b0, b1);
            }
        }

        if (t < 31) {
            STORE_TILE(1 - cur);
            __syncthreads();
        }
    }

    // write C: rows mw*64 + i*16 + {r, r+8}, cols warp_n + j*8 + {2c, 2c+1}
    float* outp = g_priors + ((size_t)o * (Bb * Kk) + row0) * Ee;
#pragma unroll
    for (int i = 0; i < 4; i++) {
#pragma unroll
        for (int j = 0; j < 4; j++) {
            int m = mw * 64 + i * 16 + r;
            int n = warp_n + j * 8 + 2 * c;
            *reinterpret_cast<float2*>(&outp[(size_t)m * Ee + n])       = make_float2(acc[i][j][0], acc[i][j][1]);
            *reinterpret_cast<float2*>(&outp[(size_t)(m + 8) * Ee + n]) = make_float2(acc[i][j][2], acc[i][j][3]);
        }
    }

    // fused iter-0 k-partials: warp covers a full 64-row half x 32 columns
    {
        const int h = mw;
#pragma unroll
        for (int j = 0; j < 4; j++) {
            float s0 = 0.f, s1 = 0.f;
#pragma unroll
            for (int i = 0; i < 4; i++) {
                s0 += acc[i][j][0] + acc[i][j][2];
                s1 += acc[i][j][1] + acc[i][j][3];
            }
#pragma unroll
            for (int off = 4; off <= 16; off <<= 1) {
                s0 += __shfl_xor_sync(0xffffffffu, s0, off);
                s1 += __shfl_xor_sync(0xffffffffu, s1, off);
            }
            if (lane < 4) {
                int col = warp_n + j * 8 + 2 * lane;
                float* sp = &g_spart[((size_t)(tile * 2 + h) * 48 + b * Oo + o) * Ee];
                sp[col]     = s0 * (1.f / 6.f);
                sp[col + 1] = s1 * (1.f / 6.f);
            }
        }
    }
#undef LOAD_TILE
#undef STORE_TILE
}

// ---------------------------------------------------------------------------
// Kernel 2: fused routing iteration with inline v computation.
// grid (8 b, 16 sl) x 256 threads.
// ---------------------------------------------------------------------------
__global__ void __launch_bounds__(256) fused_iter(const int* __restrict__ mask, int first) {
    const int b    = blockIdx.x;
    const int sl   = blockIdx.y;   // 0..15
    const int tid  = threadIdx.x;
    const int w    = tid >> 5;
    const int lane = tid & 31;

    __shared__ float vsh[Oo * Ee];

    for (int i = tid; i < Oo * Ee; i += 256) {
        int o = i >> 7, e = i & 127;
        float s = 0.f;
#pragma unroll
        for (int q = 0; q < 16; q++)
            s += g_spart[(q * 48 + b * Oo + o) * Ee + e];
        vsh[i] = s;
    }
    __syncthreads();
    if (w < Oo) {
        float4 sv = *reinterpret_cast<float4*>(&vsh[w * Ee + lane * 4]);
        float x2 = sv.x * sv.x + sv.y * sv.y + sv.z * sv.z + sv.w * sv.w;
#pragma unroll
        for (int off = 16; off > 0; off >>= 1)
            x2 += __shfl_xor_sync(0xffffffffu, x2, off);
        float coef = x2 / ((1.f + x2) * (sqrtf(x2) + EPSf));
        sv.x *= coef; sv.y *= coef; sv.z *= coef; sv.w *= coef;
        *reinterpret_cast<float4*>(&vsh[w * Ee + lane * 4]) = sv;
    }
    __syncthreads();

    float4 vv[Oo];
#pragma unroll
    for (int o = 0; o < Oo; o++)
        vv[o] = *reinterpret_cast<const float4*>(&vsh[o * Ee + lane * 4]);

    float4 sacc[Oo];
#pragma unroll
    for (int o = 0; o < Oo; o++) sacc[o] = make_float4(0.f, 0.f, 0.f, 0.f);

#pragma unroll 1
    for (int t = 0; t < 8; t++) {
        const int k   = sl * 64 + w * 8 + t;
        const int idx = b * Kk + k;

        float4 P4[Oo];
#pragma unroll
        for (int o = 0; o < Oo; o++)
            P4[o] = *reinterpret_cast<const float4*>(
                &g_priors[((size_t)(o * Bb + b) * Kk + k) * Ee + lane * 4]);

        const int m = mask[idx];
        float p[Oo];
        if (m) {
#pragma unroll
            for (int o = 0; o < Oo; o++) p[o] = 1.f / 6.f;
        } else {
            float d[Oo];
#pragma unroll
            for (int o = 0; o < Oo; o++)
                d[o] = P4[o].x * vv[o].x + P4[o].y * vv[o].y + P4[o].z * vv[o].z + P4[o].w * vv[o].w;
#pragma unroll
            for (int off = 16; off > 0; off >>= 1)
#pragma unroll
                for (int o = 0; o < Oo; o++)
                    d[o] += __shfl_xor_sync(0xffffffffu, d[o], off);

            float lg[Oo];
            if (first) {
#pragma unroll
                for (int o = 0; o < Oo; o++) lg[o] = d[o];
            } else {
                float myold = (lane < Oo) ? g_logits[(size_t)idx * Oo + lane] : 0.f;
#pragma unroll
                for (int o = 0; o < Oo; o++)
                    lg[o] = __shfl_sync(0xffffffffu, myold, o) + d[o];
            }
            if (lane < Oo) g_logits[(size_t)idx * Oo + lane] = lg[lane];

            float mx = lg[0];
#pragma unroll
            for (int o = 1; o < Oo; o++) mx = fmaxf(mx, lg[o]);
            float sum = 0.f;
#pragma unroll
            for (int o = 0; o < Oo; o++) { p[o] = __expf(lg[o] - mx); sum += p[o]; }
            float inv = 1.f / sum;
#pragma unroll
            for (int o = 0; o < Oo; o++) p[o] *= inv;
        }

        if (lane < Oo) g_probs[(size_t)idx * Oo + lane] = p[lane];

#pragma unroll
        for (int o = 0; o < Oo; o++) {
            sacc[o].x += p[o] * P4[o].x;
            sacc[o].y += p[o] * P4[o].y;
            sacc[o].z += p[o] * P4[o].z;
            sacc[o].w += p[o] * P4[o].w;
        }
    }

    __shared__ float sred[8][Oo * Ee];
#pragma unroll
    for (int o = 0; o < Oo; o++)
        *reinterpret_cast<float4*>(&sred[w][o * Ee + lane * 4]) = sacc[o];
    __syncthreads();

    for (int i = tid; i < Oo * Ee; i += 256) {
        float s = 0.f;
#pragma unroll
        for (int ww = 0; ww < 8; ww++) s += sred[ww][i];
        g_spart[(sl * 48 + b * Oo + (i >> 7)) * Ee + (i & 127)] = s;
    }
}

// ---------------------------------------------------------------------------
// Kernel 3: final squash + v broadcast, parallel over L. grid (48, 8) x 256.
// ---------------------------------------------------------------------------
__global__ void __launch_bounds__(256) squash_bcast_v(float* __restrict__ out_v) {
    const int bo  = blockIdx.x;  // b*Oo + o
    const int lc  = blockIdx.y;  // 0..7
    const int b   = bo / Oo;
    const int o   = bo % Oo;
    const int tid = threadIdx.x;

    __shared__ float s_store[Ee];
    __shared__ float ws[4];
    __shared__ float vsh[Ee];

    if (tid < 128) {
        float s = 0.f;
#pragma unroll
        for (int q = 0; q < 16; q++)
            s += g_spart[(q * 48 + bo) * Ee + tid];
        s_store[tid] = s;
        float x2 = s * s;
#pragma unroll
        for (int off = 16; off > 0; off >>= 1)
            x2 += __shfl_xor_sync(0xffffffffu, x2, off);
        if ((tid & 31) == 0) ws[tid >> 5] = x2;
    }
    __syncthreads();
    if (tid < 128) {
        float sq   = ws[0] + ws[1] + ws[2] + ws[3];
        float coef = sq / ((1.f + sq) * (sqrtf(sq) + EPSf));
        vsh[tid]   = s_store[tid] * coef;
    }
    __syncthreads();

    const float4 myval = reinterpret_cast<const float4*>(vsh)[tid & 31];
    for (int idx = tid; idx < 128 * 32; idx += 256) {
        int l = lc * 128 + (idx >> 5);
        reinterpret_cast<float4*>(out_v)[((size_t)(b * Ll + l) * Oo + o) * 32 + (tid & 31)] = myval;
    }
}

// ---------------------------------------------------------------------------
// Kernel 4: broadcast probs[b,k,o] -> out_p[b,l,k,o].
// One block per (b, 8 l's): stage the 24KB slice in registers, write 8x.
// ---------------------------------------------------------------------------
__global__ void __launch_bounds__(256) bcast_probs(float* __restrict__ out, int blk0) {
    const int blk = blk0 + blockIdx.x;   // 0..1023
    const int b   = blk >> 7;            // 128 l-groups per b
    const int lg  = blk & 127;
    const int tid = threadIdx.x;

    const float4* src = reinterpret_cast<const float4*>(g_probs) + (size_t)b * (Kk * Oo / 4);
    float4 v[6];
#pragma unroll
    for (int q = 0; q < 6; q++) v[q] = src[tid + q * 256];

#pragma unroll
    for (int l = 0; l < 8; l++) {
        float4* dst = reinterpret_cast<float4*>(out) +
                      ((size_t)(b * Ll + lg * 8 + l)) * (Kk * Oo / 4);
#pragma unroll
        for (int q = 0; q < 6; q++) dst[tid + q * 256] = v[q];
    }
}

// ---------------------------------------------------------------------------
extern "C" void kernel_launch(void* const* d_in, const int* in_sizes, int n_in,
                              void* d_out, int out_size) {
    const float* U = (const float*)d_in[0];               // inputs_u (B,K,D)
    // d_in[1] = context_sequence : provably unused by the reference math
    const float* W = (const float*)d_in[2];               // route_weights (O,D,E)
    const int* mask = (const int*)d_in[3];                // inputs_mask (B,K), bool->int32

    float* out_v = (float*)d_out;                                   // (B,L,O,E)
    float* out_p = (float*)d_out + (size_t)Bb * Ll * Oo * Ee;       // (B,L,K,O)

    // 1. priors GEMM (fp16 mma.sync, fp32 accum) + fused iter-0 k-partials
    gemm_priors<<<dim3((Bb * Kk) / 128, Oo), 256>>>(U, W);

    // 2. Routing iterations; v computed inline from spart each time
    fused_iter<<<dim3(Bb, 16), 256>>>(mask, 1);  // v0 -> logits1, probs1, spart
    fused_iter<<<dim3(Bb, 16), 256>>>(mask, 0);  // v1 -> logits2, probs2, spart

    // 3. Final squash + v broadcast (parallel over L); probs broadcast
    squash_bcast_v<<<dim3(48, 8), 256>>>(out_v);
    bcast_probs<<<512, 256>>>(out_p, 0);
    bcast_probs<<<512, 256>>>(out_p, 512);
}

// round 12
// speedup vs baseline: 1.8724x; 1.0620x over previous
#include <cuda_runtime.h>
#include <cuda_fp16.h>
#include <cstdint>

// Problem dims
#define Bb 8
#define Kk 1024
#define Ll 1024
#define Dd 1024
#define Oo 6
#define Ee 128
#define EPSf 1e-8f

// Scratch (device globals: allocation-free)
__device__ float g_priors[(size_t)Oo * Bb * Kk * Ee];  // [o][b][k][e]  (25 MB)
__device__ float g_logits[Bb * Kk * Oo];
__device__ float g_probs[Bb * Kk * Oo];                // [b][k][o]
// Ping-pong k-partial buffers: buf0 at offset 0, buf1 at SPOFF. 32 slices max.
#define SPOFF (32 * 48 * Ee)
__device__ float g_spart[2 * 32 * 48 * Ee];

__device__ __forceinline__ unsigned packh2(float lo, float hi) {
    __half2 t = __floats2half2_rn(lo, hi);
    return *reinterpret_cast<unsigned*>(&t);
}
__device__ __forceinline__ void mma_f16(float* c, const unsigned* a, unsigned b0, unsigned b1) {
    asm volatile(
        "mma.sync.aligned.m16n8k16.row.col.f32.f16.f16.f32 "
        "{%0,%1,%2,%3}, {%4,%5,%6,%7}, {%8,%9}, {%0,%1,%2,%3};\n"
        : "+f"(c[0]), "+f"(c[1]), "+f"(c[2]), "+f"(c[3])
        : "r"(a[0]), "r"(a[1]), "r"(a[2]), "r"(a[3]), "r"(b0), "r"(b1));
}

// ---------------------------------------------------------------------------
// Kernel 1: priors GEMM, fp16 mma.sync m16n8k16 (fp32 accum), warp tile
// 64m x 32n, fragment-packed A, k-pair-packed B, double-buffered smem,
// fused iter-0 k-partials -> g_spart buf0 slices 0..15.
// grid (64 row-tiles of 128, 6 o) x 256 threads.   [unchanged from R11]
// ---------------------------------------------------------------------------
#define BPAD 132

__global__ void __launch_bounds__(256) gemm_priors(const float* __restrict__ U,
                                                   const float* __restrict__ W) {
    const int o    = blockIdx.y;
    const int row0 = blockIdx.x * 128;
    const int b    = blockIdx.x >> 3;   // 8 tiles per b
    const int tile = blockIdx.x & 7;

    const int tid  = threadIdx.x;
    const int lane = tid & 31;
    const int wid  = tid >> 5;
    const int mw     = wid & 1;          // m-warp: rows mw*64 .. +63
    const int warp_n = (wid >> 1) * 32;  // n-warp: cols warp_n .. +31
    const int r    = lane >> 2;          // 0..7
    const int c    = lane & 3;           // 0..3

    __shared__ unsigned Af[2][2048];         // packed A halves, 8KB per stage
    __shared__ unsigned Bp[2][16 * BPAD];    // packed B halves, 8.25KB per stage

    const float* Wo = W + (size_t)o * Dd * Ee;

    float acc[4][4][4];
#pragma unroll
    for (int i = 0; i < 4; i++)
#pragma unroll
        for (int j = 0; j < 4; j++)
#pragma unroll
            for (int q = 0; q < 4; q++) acc[i][j][q] = 0.f;

    float4 aST[4], bLO[2], bHI[2];

#define LOAD_TILE(k0)                                                                   \
    {                                                                                   \
        _Pragma("unroll")                                                               \
        for (int i_ = 0; i_ < 4; i_++) {                                                \
            int f = tid + i_ * 256;                                                     \
            aST[i_] = *reinterpret_cast<const float4*>(                                 \
                &U[(size_t)(row0 + (f >> 3)) * Dd + (k0) + (f & 7) * 4]);               \
        }                                                                               \
        _Pragma("unroll")                                                               \
        for (int i_ = 0; i_ < 2; i_++) {                                                \
            int f  = tid + i_ * 256;                                                    \
            int kp = f >> 5;                                                            \
            int n4 = (f & 31) * 4;                                                      \
            bLO[i_] = *reinterpret_cast<const float4*>(                                 \
                &Wo[(size_t)((k0) + 2 * kp) * Ee + n4]);                                \
            bHI[i_] = *reinterpret_cast<const float4*>(                                 \
                &Wo[(size_t)((k0) + 2 * kp + 1) * Ee + n4]);                            \
        }                                                                               \
    }
#define STORE_TILE(buf)                                                                 \
    {                                                                                   \
        _Pragma("unroll")                                                               \
        for (int i_ = 0; i_ < 4; i_++) {                                                \
            int f  = tid + i_ * 256;                                                    \
            int m  = f >> 3;                                                            \
            int g  = f & 7;                                                             \
            int ks = g >> 2;                                                            \
            int p0 = (g & 3) * 2;                                                       \
            int base = ((m >> 4) * 2 + ks) * 128 + (m & 7) * 16 + ((m >> 3) & 1);       \
            Af[buf][base + (p0 & 3) * 4 + 2 * (p0 >> 2)] = packh2(aST[i_].x, aST[i_].y);\
            int p1 = p0 + 1;                                                            \
            Af[buf][base + (p1 & 3) * 4 + 2 * (p1 >> 2)] = packh2(aST[i_].z, aST[i_].w);\
        }                                                                               \
        _Pragma("unroll")                                                               \
        for (int i_ = 0; i_ < 2; i_++) {                                                \
            int f  = tid + i_ * 256;                                                    \
            int kp = f >> 5;                                                            \
            int n4 = (f & 31) * 4;                                                      \
            *reinterpret_cast<uint4*>(&Bp[buf][kp * BPAD + n4]) =                       \
                make_uint4(packh2(bLO[i_].x, bHI[i_].x), packh2(bLO[i_].y, bHI[i_].y),  \
                           packh2(bLO[i_].z, bHI[i_].z), packh2(bLO[i_].w, bHI[i_].w)); \
        }                                                                               \
    }

    LOAD_TILE(0);
    STORE_TILE(0);
    __syncthreads();

    for (int t = 0; t < 32; t++) {
        const int cur = t & 1;
        if (t < 31) LOAD_TILE((t + 1) * 32);

#pragma unroll
        for (int ks = 0; ks < 2; ks++) {
            uint4 afr[4];
#pragma unroll
            for (int i = 0; i < 4; i++)
                afr[i] = *reinterpret_cast<const uint4*>(
                    &Af[cur][((mw * 4 + i) * 2 + ks) * 128 + r * 16 + c * 4]);
#pragma unroll
            for (int j = 0; j < 4; j++) {
                const int nb = warp_n + j * 8;
                unsigned b0 = Bp[cur][(ks * 8 + c) * BPAD + nb + r];
                unsigned b1 = Bp[cur][(ks * 8 + c + 4) * BPAD + nb + r];
#pragma unroll
                for (int i = 0; i < 4; i++)
                    mma_f16(acc[i][j], reinterpret_cast<const unsigned*>(&afr[i]), b0, b1);
            }
        }

        if (t < 31) {
            STORE_TILE(1 - cur);
            __syncthreads();
        }
    }

    float* outp = g_priors + ((size_t)o * (Bb * Kk) + row0) * Ee;
#pragma unroll
    for (int i = 0; i < 4; i++) {
#pragma unroll
        for (int j = 0; j < 4; j++) {
            int m = mw * 64 + i * 16 + r;
            int n = warp_n + j * 8 + 2 * c;
            *reinterpret_cast<float2*>(&outp[(size_t)m * Ee + n])       = make_float2(acc[i][j][0], acc[i][j][1]);
            *reinterpret_cast<float2*>(&outp[(size_t)(m + 8) * Ee + n]) = make_float2(acc[i][j][2], acc[i][j][3]);
        }
    }

    // fused iter-0 k-partials -> buf0 slices (tile*2 + half)
    {
        const int h = mw;
#pragma unroll
        for (int j = 0; j < 4; j++) {
            float s0 = 0.f, s1 = 0.f;
#pragma unroll
            for (int i = 0; i < 4; i++) {
                s0 += acc[i][j][0] + acc[i][j][2];
                s1 += acc[i][j][1] + acc[i][j][3];
            }
#pragma unroll
            for (int off = 4; off <= 16; off <<= 1) {
                s0 += __shfl_xor_sync(0xffffffffu, s0, off);
                s1 += __shfl_xor_sync(0xffffffffu, s1, off);
            }
            if (lane < 4) {
                int col = warp_n + j * 8 + 2 * lane;
                float* sp = &g_spart[((size_t)(tile * 2 + h) * 48 + b * Oo + o) * Ee];
                sp[col]     = s0 * (1.f / 6.f);
                sp[col + 1] = s1 * (1.f / 6.f);
            }
        }
    }
#undef LOAD_TILE
#undef STORE_TILE
}

// ---------------------------------------------------------------------------
// Kernel 2: fused routing iteration, ping-pong spart buffers (race-free by
// construction). grid (8 b, 32 sl) x 256 threads; warp handles 4 k's.
//   in:  g_spart + in_off,  nsl_in slices    out: g_spart + out_off, slice sl
// ---------------------------------------------------------------------------
__global__ void __launch_bounds__(256) fused_iter(const int* __restrict__ mask, int first,
                                                  int in_off, int out_off, int nsl_in) {
    const int b    = blockIdx.x;
    const int sl   = blockIdx.y;   // 0..31
    const int tid  = threadIdx.x;
    const int w    = tid >> 5;
    const int lane = tid & 31;

    __shared__ float vsh[Oo * Ee];

    const float* spin = g_spart + in_off;
    // phase 1: reduce spart -> s
    for (int i = tid; i < Oo * Ee; i += 256) {
        int o = i >> 7, e = i & 127;
        float s = 0.f;
        for (int q = 0; q < nsl_in; q++)
            s += spin[(q * 48 + b * Oo + o) * Ee + e];
        vsh[i] = s;
    }
    __syncthreads();
    // phase 2: squash per o
    if (w < Oo) {
        float4 sv = *reinterpret_cast<float4*>(&vsh[w * Ee + lane * 4]);
        float x2 = sv.x * sv.x + sv.y * sv.y + sv.z * sv.z + sv.w * sv.w;
#pragma unroll
        for (int off = 16; off > 0; off >>= 1)
            x2 += __shfl_xor_sync(0xffffffffu, x2, off);
        float coef = x2 / ((1.f + x2) * (sqrtf(x2) + EPSf));
        sv.x *= coef; sv.y *= coef; sv.z *= coef; sv.w *= coef;
        *reinterpret_cast<float4*>(&vsh[w * Ee + lane * 4]) = sv;
    }
    __syncthreads();

    float4 vv[Oo];
#pragma unroll
    for (int o = 0; o < Oo; o++)
        vv[o] = *reinterpret_cast<const float4*>(&vsh[o * Ee + lane * 4]);

    float4 sacc[Oo];
#pragma unroll
    for (int o = 0; o < Oo; o++) sacc[o] = make_float4(0.f, 0.f, 0.f, 0.f);

#pragma unroll 1
    for (int t = 0; t < 4; t++) {
        const int k   = sl * 32 + w * 4 + t;
        const int idx = b * Kk + k;

        float4 P4[Oo];
#pragma unroll
        for (int o = 0; o < Oo; o++)
            P4[o] = *reinterpret_cast<const float4*>(
                &g_priors[((size_t)(o * Bb + b) * Kk + k) * Ee + lane * 4]);

        const int m = mask[idx];
        float p[Oo];
        if (m) {
#pragma unroll
            for (int o = 0; o < Oo; o++) p[o] = 1.f / 6.f;
        } else {
            float d[Oo];
#pragma unroll
            for (int o = 0; o < Oo; o++)
                d[o] = P4[o].x * vv[o].x + P4[o].y * vv[o].y + P4[o].z * vv[o].z + P4[o].w * vv[o].w;
#pragma unroll
            for (int off = 16; off > 0; off >>= 1)
#pragma unroll
                for (int o = 0; o < Oo; o++)
                    d[o] += __shfl_xor_sync(0xffffffffu, d[o], off);

            float lg[Oo];
            if (first) {
#pragma unroll
                for (int o = 0; o < Oo; o++) lg[o] = d[o];
            } else {
                float myold = (lane < Oo) ? g_logits[(size_t)idx * Oo + lane] : 0.f;
#pragma unroll
                for (int o = 0; o < Oo; o++)
                    lg[o] = __shfl_sync(0xffffffffu, myold, o) + d[o];
            }
            if (lane < Oo) g_logits[(size_t)idx * Oo + lane] = lg[lane];

            float mx = lg[0];
#pragma unroll
            for (int o = 1; o < Oo; o++) mx = fmaxf(mx, lg[o]);
            float sum = 0.f;
#pragma unroll
            for (int o = 0; o < Oo; o++) { p[o] = __expf(lg[o] - mx); sum += p[o]; }
            float inv = 1.f / sum;
#pragma unroll
            for (int o = 0; o < Oo; o++) p[o] *= inv;
        }

        if (lane < Oo) g_probs[(size_t)idx * Oo + lane] = p[lane];

#pragma unroll
        for (int o = 0; o < Oo; o++) {
            sacc[o].x += p[o] * P4[o].x;
            sacc[o].y += p[o] * P4[o].y;
            sacc[o].z += p[o] * P4[o].z;
            sacc[o].w += p[o] * P4[o].w;
        }
    }

    // block reduction of per-warp partials -> out slice sl
    __shared__ float sred[8][Oo * Ee];
#pragma unroll
    for (int o = 0; o < Oo; o++)
        *reinterpret_cast<float4*>(&sred[w][o * Ee + lane * 4]) = sacc[o];
    __syncthreads();

    float* spout = g_spart + out_off;
    for (int i = tid; i < Oo * Ee; i += 256) {
        float s = 0.f;
#pragma unroll
        for (int ww = 0; ww < 8; ww++) s += sred[ww][i];
        spout[(sl * 48 + b * Oo + (i >> 7)) * Ee + (i & 127)] = s;
    }
}

// ---------------------------------------------------------------------------
// Kernel 3: ALL output writes in one launch (probs bcast + v squash/bcast run
// concurrently across SMs; both depend only on iter-2 results).
// grid 1408 x 256:  blocks [0,1024) probs, [1024,1408) v.
// ---------------------------------------------------------------------------
__global__ void __launch_bounds__(256) write_outputs(float* __restrict__ out_v,
                                                     float* __restrict__ out_p) {
    const int tid = threadIdx.x;

    if (blockIdx.x < 1024) {
        // probs: one block per (b, 8 l's), register-staged
        const int blk = blockIdx.x;
        const int b   = blk >> 7;
        const int lg  = blk & 127;

        const float4* src = reinterpret_cast<const float4*>(g_probs) + (size_t)b * (Kk * Oo / 4);
        float4 v[6];
#pragma unroll
        for (int q = 0; q < 6; q++) v[q] = src[tid + q * 256];

#pragma unroll
        for (int l = 0; l < 8; l++) {
            float4* dst = reinterpret_cast<float4*>(out_p) +
                          ((size_t)(b * Ll + lg * 8 + l)) * (Kk * Oo / 4);
#pragma unroll
            for (int q = 0; q < 6; q++) dst[tid + q * 256] = v[q];
        }
    } else {
        // v: squash (32 slices, buf0) + broadcast 128 l's
        const int q2 = blockIdx.x - 1024;  // 0..383
        const int bo = q2 >> 3;            // b*Oo + o
        const int lc = q2 & 7;
        const int b  = bo / Oo;
        const int o  = bo % Oo;

        __shared__ float s_store[Ee];
        __shared__ float ws[4];
        __shared__ float vsh[Ee];

        if (tid < 128) {
            float s = 0.f;
#pragma unroll
            for (int q = 0; q < 32; q++)
                s += g_spart[(q * 48 + bo) * Ee + tid];
            s_store[tid] = s;
            float x2 = s * s;
#pragma unroll
            for (int off = 16; off > 0; off >>= 1)
                x2 += __shfl_xor_sync(0xffffffffu, x2, off);
            if ((tid & 31) == 0) ws[tid >> 5] = x2;
        }
        __syncthreads();
        if (tid < 128) {
            float sq   = ws[0] + ws[1] + ws[2] + ws[3];
            float coef = sq / ((1.f + sq) * (sqrtf(sq) + EPSf));
            vsh[tid]   = s_store[tid] * coef;
        }
        __syncthreads();

        const float4 myval = reinterpret_cast<const float4*>(vsh)[tid & 31];
        for (int idx = tid; idx < 128 * 32; idx += 256) {
            int l = lc * 128 + (idx >> 5);
            reinterpret_cast<float4*>(out_v)[((size_t)(b * Ll + l) * Oo + o) * 32 + (tid & 31)] = myval;
        }
    }
}

// ---------------------------------------------------------------------------
extern "C" void kernel_launch(void* const* d_in, const int* in_sizes, int n_in,
                              void* d_out, int out_size) {
    const float* U = (const float*)d_in[0];               // inputs_u (B,K,D)
    // d_in[1] = context_sequence : provably unused by the reference math
    const float* W = (const float*)d_in[2];               // route_weights (O,D,E)
    const int* mask = (const int*)d_in[3];                // inputs_mask (B,K), bool->int32

    float* out_v = (float*)d_out;                                   // (B,L,O,E)
    float* out_p = (float*)d_out + (size_t)Bb * Ll * Oo * Ee;       // (B,L,K,O)

    // 1. priors GEMM (fp16 mma.sync, fp32 accum) -> priors + buf0 slices 0..15
    gemm_priors<<<dim3((Bb * Kk) / 128, Oo), 256>>>(U, W);

    // 2. Routing iterations, ping-pong spart (buf0 -> buf1 -> buf0)
    fused_iter<<<dim3(Bb, 32), 256>>>(mask, 1, 0, SPOFF, 16);  // v0 -> logits1/probs1
    fused_iter<<<dim3(Bb, 32), 256>>>(mask, 0, SPOFF, 0, 32);  // v1 -> logits2/probs2

    // 3. All outputs in one launch (probs bcast || v squash+bcast)
    write_outputs<<<1408, 256>>>(out_v, out_p);
}